// round 3
// baseline (speedup 1.0000x reference)
#include <cuda_runtime.h>
#include <math.h>

// Problem constants
#define Bn   32
#define Cn   16
#define HWn  65536
#define T1   128               // tiles per batch, pass1
#define T3   128               // tiles per batch, pass3
#define PPB  512               // pixels per block (both passes)
#define THREADS 256            // 2 pixels per thread, single iteration

// Scratch (__device__ globals; overwritten each run, no zeroing needed)
__device__ float g_part[2][Bn][32][T1];   // [tensor][batch][slot: 0-15 tot, 16-31 cls0][tile]
__device__ float g_cnt[Bn][T1];           // class-0 pixel count partials
__device__ float g_msep[Bn * T3];         // per-block MSE partials
__device__ unsigned int g_done;           // last-block counter (self-resetting)

__device__ __forceinline__ float wred(float v) {
    v += __shfl_down_sync(0xFFFFFFFFu, v, 16);
    v += __shfl_down_sync(0xFFFFFFFFu, v, 8);
    v += __shfl_down_sync(0xFFFFFFFFu, v, 4);
    v += __shfl_down_sync(0xFFFFFFFFu, v, 2);
    v += __shfl_down_sync(0xFFFFFFFFu, v, 1);
    return v;
}
__device__ __forceinline__ double wredd(double v) {
    v += __shfl_down_sync(0xFFFFFFFFu, v, 16);
    v += __shfl_down_sync(0xFFFFFFFFu, v, 8);
    v += __shfl_down_sync(0xFFFFFFFFu, v, 4);
    v += __shfl_down_sync(0xFFFFFFFFu, v, 2);
    v += __shfl_down_sync(0xFFFFFFFFu, v, 1);
    return v;
}

// Per-block dtype sniff: int64 targets with values in {0,1} have all odd
// 32-bit words zero. All blocks read the same 512 words -> identical result.
__device__ __forceinline__ int sniff_is32(const int* __restrict__ tw, int tid) {
    int any = 0;
#pragma unroll
    for (int i = tid; i < 512; i += THREADS) any |= tw[2 * i + 1];
    return __syncthreads_or(any);
}

__device__ __forceinline__ void load_cls2(const int* __restrict__ twb, int p, int is32,
                                          int& c0, int& c1) {
    if (is32) {
        int2 v = *(const int2*)(twb + p);
        c0 = v.x; c1 = v.y;
    } else {
        int4 a = *(const int4*)(twb + 2 * p);
        c0 = a.x; c1 = a.z;
    }
}

// ---------------------------------------------------------------------------
// Pass 1: per-(tensor,batch,tile) partial sums of L2-normalized features.
// grid (T1, Bn, 2); 512 px/block, 2 px/thread, float2 loads, 1 iteration.
// ---------------------------------------------------------------------------
__global__ void __launch_bounds__(THREADS, 3)
pass1_kernel(const float* __restrict__ S, const float* __restrict__ T,
             const int* __restrict__ TW) {
    const int tile = blockIdx.x, b = blockIdx.y, z = blockIdx.z;
    const int tid  = threadIdx.x;
    const int is32 = sniff_is32(TW, tid);

    const float* Xb  = (z ? T : S) + ((size_t)b << 20);
    const int*   twb = TW + (is32 ? ((size_t)b << 16) : ((size_t)b << 17));

    const int p = tile * PPB + tid * 2;
    int c0, c1;
    load_cls2(twb, p, is32, c0, c1);
    const float m0 = (c0 == 0) ? 1.f : 0.f;
    const float m1 = (c1 == 0) ? 1.f : 0.f;
    float cnt = m0 + m1;

    float2 v[Cn];
#pragma unroll
    for (int c = 0; c < Cn; c++) v[c] = *(const float2*)(Xb + ((size_t)c << 16) + p);

    float n0 = 0.f, n1 = 0.f;
#pragma unroll
    for (int c = 0; c < Cn; c++) {
        n0 = fmaf(v[c].x, v[c].x, n0);
        n1 = fmaf(v[c].y, v[c].y, n1);
    }
    const float i0 = rsqrtf(fmaxf(n0, 1e-24f));
    const float i1 = rsqrtf(fmaxf(n1, 1e-24f));

    float at[Cn], a0[Cn];
#pragma unroll
    for (int c = 0; c < Cn; c++) {
        const float f0 = v[c].x * i0;
        const float f1 = v[c].y * i1;
        at[c] = f0 + f1;
        a0[c] = fmaf(m0, f0, m1 * f1);
    }

    // Block reduce 33 slots; write partials (no atomics).
    __shared__ float sred[THREADS / 32][33];
    const int lane = tid & 31, w = tid >> 5;
#pragma unroll
    for (int c = 0; c < Cn; c++) { at[c] = wred(at[c]); a0[c] = wred(a0[c]); }
    cnt = wred(cnt);
    if (lane == 0) {
#pragma unroll
        for (int c = 0; c < Cn; c++) { sred[w][c] = at[c]; sred[w][16 + c] = a0[c]; }
        sred[w][32] = cnt;
    }
    __syncthreads();
    if (tid < 33) {
        float s = 0.f;
#pragma unroll
        for (int ww = 0; ww < THREADS / 32; ww++) s += sred[ww][tid];
        if (tid < 32)      g_part[z][b][tid][tile] = s;
        else if (z == 0)   g_cnt[b][tile] = s;
    }
}

// ---------------------------------------------------------------------------
// Pass 3: prologue computes class means from partials (L2 reads), then
// streaming per-pixel cosines + MSE; last block finishes the reduction.
// grid (T3, Bn); 512 px/block, 2 px/thread, float2 loads, 1 iteration.
// ---------------------------------------------------------------------------
__global__ void __launch_bounds__(THREADS, 4)
pass3_kernel(const float* __restrict__ S, const float* __restrict__ T,
             const int* __restrict__ TW, float* __restrict__ out) {
    const int tile = blockIdx.x, b = blockIdx.y;
    const int tid  = threadIdx.x;
    const int is32 = sniff_is32(TW, tid);

    __shared__ float sq[4][64];     // quarter-partials per slot (slot = z*32+i)
    __shared__ float red[64];
    __shared__ float scq[4];
    __shared__ float smM[2][2][Cn]; // [tensor][cls][channel]
    __shared__ float smN[2][2];
    __shared__ unsigned int slast;

    // Reduce g_part over tiles: 256 threads = 64 slots x 4 quarters (32 tiles ea).
    {
        const int s = tid & 63, q = tid >> 6;
        const int z = s >> 5, i = s & 31;
        const float* base = &g_part[z][b][i][0] + q * 32;
        float a = 0.f;
#pragma unroll
        for (int k = 0; k < 8; k++) {
            const float4 v = *(const float4*)(base + 4 * k);
            a += (v.x + v.y) + (v.z + v.w);
        }
        sq[q][s] = a;
    }
    __syncthreads();
    if (tid < 64) {
        red[tid] = ((sq[0][tid] + sq[1][tid]) + (sq[2][tid] + sq[3][tid]));
    } else if (tid < 68) {
        const int q = tid - 64;
        const float* cb = &g_cnt[b][0] + q * 32;
        float a = 0.f;
#pragma unroll
        for (int k = 0; k < 8; k++) {
            const float4 v = *(const float4*)(cb + 4 * k);
            a += (v.x + v.y) + (v.z + v.w);
        }
        scq[q] = a;
    }
    __syncthreads();
    if (tid < 4) {
        const int z = tid >> 1, cls = tid & 1;
        const float cnt0 = (scq[0] + scq[1]) + (scq[2] + scq[3]);
        const float cnt  = cls ? ((float)HWn - cnt0) : cnt0;
        const float inv  = 1.0f / (cnt + 1e-6f);
        float nm2 = 0.f;
#pragma unroll
        for (int c = 0; c < Cn; c++) {
            const float tot = red[z * 32 + c];
            const float s0  = red[z * 32 + 16 + c];
            const float sv  = cls ? (tot - s0) : s0;
            const float m   = sv * inv;
            smM[z][cls][c] = m;
            nm2 = fmaf(m, m, nm2);
        }
        smN[z][cls] = sqrtf(nm2);
    }
    __syncthreads();

    const float* Sb  = S + ((size_t)b << 20);
    const float* Tb  = T + ((size_t)b << 20);
    const int*   twb = TW + (is32 ? ((size_t)b << 16) : ((size_t)b << 17));
    const float nS0 = smN[0][0], nS1 = smN[0][1];
    const float nT0 = smN[1][0], nT1 = smN[1][1];

    const int p = tile * PPB + tid * 2;
    int c0, c1;
    load_cls2(twb, p, is32, c0, c1);
    const float s0 = (c0 == 0) ? 1.f : -1.f;
    const float s1 = (c1 == 0) ? 1.f : -1.f;

    float pcS0, pcS1;
    {   // ---- S (streamed) ----
        float n0 = 0.f, n1 = 0.f, dA0 = 0.f, dB0 = 0.f, dA1 = 0.f, dB1 = 0.f;
#pragma unroll
        for (int c = 0; c < Cn; c++) {
            const float2 v = *(const float2*)(Sb + ((size_t)c << 16) + p);
            const float mA = smM[0][0][c], mB = smM[0][1][c];
            n0 = fmaf(v.x, v.x, n0); n1 = fmaf(v.y, v.y, n1);
            dA0 = fmaf(v.x, mA, dA0); dB0 = fmaf(v.x, mB, dB0);
            dA1 = fmaf(v.y, mA, dA1); dB1 = fmaf(v.y, mB, dB1);
        }
        const float i0 = rsqrtf(fmaxf(n0, 1e-24f)), i1 = rsqrtf(fmaxf(n1, 1e-24f));
        const float f0 = sqrtf(n0) * i0, f1 = sqrtf(n1) * i1;
        const float cd0 = (dA0 * i0) / fmaxf(f0 * nS0, 1e-8f) - (dB0 * i0) / fmaxf(f0 * nS1, 1e-8f);
        const float cd1 = (dA1 * i1) / fmaxf(f1 * nS0, 1e-8f) - (dB1 * i1) / fmaxf(f1 * nS1, 1e-8f);
        pcS0 = expf(s0 * cd0); pcS1 = expf(s1 * cd1);
    }
    float acc;
    {   // ---- T (streamed) ----
        float n0 = 0.f, n1 = 0.f, dA0 = 0.f, dB0 = 0.f, dA1 = 0.f, dB1 = 0.f;
#pragma unroll
        for (int c = 0; c < Cn; c++) {
            const float2 v = *(const float2*)(Tb + ((size_t)c << 16) + p);
            const float mA = smM[1][0][c], mB = smM[1][1][c];
            n0 = fmaf(v.x, v.x, n0); n1 = fmaf(v.y, v.y, n1);
            dA0 = fmaf(v.x, mA, dA0); dB0 = fmaf(v.x, mB, dB0);
            dA1 = fmaf(v.y, mA, dA1); dB1 = fmaf(v.y, mB, dB1);
        }
        const float i0 = rsqrtf(fmaxf(n0, 1e-24f)), i1 = rsqrtf(fmaxf(n1, 1e-24f));
        const float f0 = sqrtf(n0) * i0, f1 = sqrtf(n1) * i1;
        const float cd0 = (dA0 * i0) / fmaxf(f0 * nT0, 1e-8f) - (dB0 * i0) / fmaxf(f0 * nT1, 1e-8f);
        const float cd1 = (dA1 * i1) / fmaxf(f1 * nT0, 1e-8f) - (dB1 * i1) / fmaxf(f1 * nT1, 1e-8f);
        const float d0 = pcS0 - expf(s0 * cd0);
        const float d1 = pcS1 - expf(s1 * cd1);
        acc = fmaf(d0, d0, d1 * d1);
    }

    // Block reduce MSE partial
    __shared__ float smse[THREADS / 32];
    acc = wred(acc);
    const int lane = tid & 31, w = tid >> 5;
    if (lane == 0) smse[w] = acc;
    __syncthreads();
    const int gid = b * T3 + tile;
    if (tid == 0) {
        float s = 0.f;
#pragma unroll
        for (int ww = 0; ww < THREADS / 32; ww++) s += smse[ww];
        g_msep[gid] = s;
        __threadfence();
        const unsigned int old = atomicAdd(&g_done, 1u);
        slast = (old == (unsigned int)(Bn * T3 - 1)) ? 1u : 0u;
    }
    __syncthreads();

    if (slast) {
        // Final reduction of 4096 partials in the last block.
        volatile float* mp = &g_msep[0];
        double d = 0.0;
#pragma unroll
        for (int k = 0; k < 16; k++) d += (double)mp[tid * 16 + k];
        d = wredd(d);
        __shared__ double sd[THREADS / 32];
        if (lane == 0) sd[w] = d;
        __syncthreads();
        if (tid == 0) {
            double tot = 0.0;
#pragma unroll
            for (int ww = 0; ww < THREADS / 32; ww++) tot += sd[ww];
            out[0] = (float)(tot * (1.0 / ((double)Bn * (double)HWn)));
            g_done = 0;   // reset for next graph replay
        }
    }
}

extern "C" void kernel_launch(void* const* d_in, const int* in_sizes, int n_in,
                              void* d_out, int out_size) {
    const float* S  = (const float*)d_in[0];
    const float* T  = (const float*)d_in[1];
    const int*   TW = (const int*)d_in[2];
    float* out = (float*)d_out;

    dim3 g1(T1, Bn, 2);
    pass1_kernel<<<g1, THREADS>>>(S, T, TW);
    dim3 g3(T3, Bn);
    pass3_kernel<<<g3, THREADS>>>(S, T, TW, out);
}

// round 4
// speedup vs baseline: 1.3646x; 1.3646x over previous
#include <cuda_runtime.h>
#include <math.h>

// Problem constants
#define Bn   32
#define Cn   16
#define HWn  65536
#define T1   128               // tiles per batch, pass1 (512 px/tile)
#define T3   128               // tiles per batch, pass3 (512 px/tile)
#define PPB  512               // pixels per block
#define THR  128               // threads per block; 4 px/thread, float4

// Scratch (__device__ globals; fully overwritten each run)
__device__ float g_part[2][Bn][32][T1];   // [tensor][batch][slot:0-15 tot,16-31 cls0][tile]
__device__ float g_cnt[Bn][T1];           // class-0 count partials (written by z==0)
__device__ float g_mean[2][Bn][2][Cn];    // [tensor][batch][cls][chan]
__device__ float g_nm[2][Bn][2];          // mean norms
__device__ float g_msep[Bn * T3];         // per-block MSE partials
__device__ unsigned int g_done;           // last-block counter (self-resetting)

__device__ __forceinline__ float wred(float v) {
    v += __shfl_down_sync(0xFFFFFFFFu, v, 16);
    v += __shfl_down_sync(0xFFFFFFFFu, v, 8);
    v += __shfl_down_sync(0xFFFFFFFFu, v, 4);
    v += __shfl_down_sync(0xFFFFFFFFu, v, 2);
    v += __shfl_down_sync(0xFFFFFFFFu, v, 1);
    return v;
}
__device__ __forceinline__ double wredd(double v) {
    v += __shfl_down_sync(0xFFFFFFFFu, v, 16);
    v += __shfl_down_sync(0xFFFFFFFFu, v, 8);
    v += __shfl_down_sync(0xFFFFFFFFu, v, 4);
    v += __shfl_down_sync(0xFFFFFFFFu, v, 2);
    v += __shfl_down_sync(0xFFFFFFFFu, v, 1);
    return v;
}

// Per-block dtype sniff: int64 targets with values in {0,1} have all odd
// 32-bit words zero; int32 targets have random labels there. All blocks read
// the same 512 words (L2-broadcast) -> identical deterministic result.
__device__ __forceinline__ int sniff_is32(const int* __restrict__ tw, int tid) {
    int any = 0;
#pragma unroll
    for (int i = tid; i < 512; i += THR) any |= tw[2 * i + 1];
    return __syncthreads_or(any);
}

__device__ __forceinline__ void load_cls4(const int* __restrict__ twb, int p, int is32,
                                          int& c0, int& c1, int& c2, int& c3) {
    if (is32) {
        int4 v = *(const int4*)(twb + p);
        c0 = v.x; c1 = v.y; c2 = v.z; c3 = v.w;
    } else {
        int4 a = *(const int4*)(twb + 2 * p);
        int4 b = *(const int4*)(twb + 2 * p + 4);
        c0 = a.x; c1 = a.z; c2 = b.x; c3 = b.z;
    }
}

// ---------------------------------------------------------------------------
// Pass 1: per-(tensor,batch,tile) partial sums of L2-normalized features.
// grid (T1, Bn, 2); 4 px/thread, float4 loads, tile held in registers.
// ---------------------------------------------------------------------------
__global__ void __launch_bounds__(THR, 4)
pass1_kernel(const float* __restrict__ S, const float* __restrict__ T,
             const int* __restrict__ TW) {
    const int tile = blockIdx.x, b = blockIdx.y, z = blockIdx.z;
    const int tid  = threadIdx.x;
    const int is32 = sniff_is32(TW, tid);

    const float* Xb  = (z ? T : S) + ((size_t)b << 20);
    const int*   twb = TW + (is32 ? ((size_t)b << 16) : ((size_t)b << 17));

    const int p = tile * PPB + tid * 4;
    int c0, c1, c2, c3;
    load_cls4(twb, p, is32, c0, c1, c2, c3);
    const float m0 = (c0 == 0) ? 1.f : 0.f;
    const float m1 = (c1 == 0) ? 1.f : 0.f;
    const float m2 = (c2 == 0) ? 1.f : 0.f;
    const float m3 = (c3 == 0) ? 1.f : 0.f;
    float cnt = (m0 + m1) + (m2 + m3);

    float4 v[Cn];
#pragma unroll
    for (int c = 0; c < Cn; c++) v[c] = *(const float4*)(Xb + ((size_t)c << 16) + p);

    float n0 = 0.f, n1 = 0.f, n2 = 0.f, n3 = 0.f;
#pragma unroll
    for (int c = 0; c < Cn; c++) {
        n0 = fmaf(v[c].x, v[c].x, n0); n1 = fmaf(v[c].y, v[c].y, n1);
        n2 = fmaf(v[c].z, v[c].z, n2); n3 = fmaf(v[c].w, v[c].w, n3);
    }
    const float i0 = rsqrtf(fmaxf(n0, 1e-24f));
    const float i1 = rsqrtf(fmaxf(n1, 1e-24f));
    const float i2 = rsqrtf(fmaxf(n2, 1e-24f));
    const float i3 = rsqrtf(fmaxf(n3, 1e-24f));

    float at[Cn], a0[Cn];
#pragma unroll
    for (int c = 0; c < Cn; c++) {
        const float f0 = v[c].x * i0, f1 = v[c].y * i1;
        const float f2 = v[c].z * i2, f3 = v[c].w * i3;
        at[c] = (f0 + f1) + (f2 + f3);
        a0[c] = (m0 * f0 + m1 * f1) + (m2 * f2 + m3 * f3);
    }

    // Block reduce 33 slots; write partials (no atomics).
    __shared__ float sred[THR / 32][33];
    const int lane = tid & 31, w = tid >> 5;
#pragma unroll
    for (int c = 0; c < Cn; c++) { at[c] = wred(at[c]); a0[c] = wred(a0[c]); }
    cnt = wred(cnt);
    if (lane == 0) {
#pragma unroll
        for (int c = 0; c < Cn; c++) { sred[w][c] = at[c]; sred[w][16 + c] = a0[c]; }
        sred[w][32] = cnt;
    }
    __syncthreads();
    if (tid < 33) {
        float s = 0.f;
#pragma unroll
        for (int ww = 0; ww < THR / 32; ww++) s += sred[ww][tid];
        if (tid < 32)      g_part[z][b][tid][tile] = s;
        else if (z == 0)   g_cnt[b][tile] = s;
    }
}

// ---------------------------------------------------------------------------
// Finalize: reduce tile partials -> class means + norms. grid (Bn, 2), 256 thr.
// ---------------------------------------------------------------------------
__global__ void finalize_kernel() {
    const int b = blockIdx.x, z = blockIdx.y;
    const int tid = threadIdx.x;

    __shared__ float s[8][32];
    __shared__ float sc[8];
    __shared__ float red[32];
    __shared__ float scnt;

    {   // 256 threads = 32 slots x 8 groups of 16 tiles
        const int slot = tid & 31, q = tid >> 5;
        const float* base = &g_part[z][b][slot][0] + q * 16;
        float a = 0.f;
#pragma unroll
        for (int k = 0; k < 4; k++) {
            const float4 v = *(const float4*)(base + 4 * k);
            a += (v.x + v.y) + (v.z + v.w);
        }
        s[q][slot] = a;
    }
    if (tid < 8) {
        const float* cb = &g_cnt[b][0] + tid * 16;
        float a = 0.f;
#pragma unroll
        for (int k = 0; k < 4; k++) {
            const float4 v = *(const float4*)(cb + 4 * k);
            a += (v.x + v.y) + (v.z + v.w);
        }
        sc[tid] = a;
    }
    __syncthreads();
    if (tid < 32) {
        float a = 0.f;
#pragma unroll
        for (int q = 0; q < 8; q++) a += s[q][tid];
        red[tid] = a;
    } else if (tid == 32) {
        float a = 0.f;
#pragma unroll
        for (int q = 0; q < 8; q++) a += sc[q];
        scnt = a;
    }
    __syncthreads();
    if (tid < 2) {
        const int cls = tid;
        const float cnt0 = scnt;
        const float cnt  = cls ? ((float)HWn - cnt0) : cnt0;
        const float inv  = 1.0f / (cnt + 1e-6f);
        float nm2 = 0.f;
#pragma unroll
        for (int c = 0; c < Cn; c++) {
            const float tot = red[c], s0 = red[16 + c];
            const float sv  = cls ? (tot - s0) : s0;
            const float m   = sv * inv;
            g_mean[z][b][cls][c] = m;
            nm2 = fmaf(m, m, nm2);
        }
        g_nm[z][b][cls] = sqrtf(nm2);
    }
}

// ---------------------------------------------------------------------------
// Pass 3: per-pixel cosines vs own/other class mean, pcsim, MSE.
// grid (T3, Bn); 4 px/thread, float4 loads, channels streamed (no held tile).
// ---------------------------------------------------------------------------
__global__ void __launch_bounds__(THR, 8)
pass3_kernel(const float* __restrict__ S, const float* __restrict__ T,
             const int* __restrict__ TW, float* __restrict__ out) {
    const int tile = blockIdx.x, b = blockIdx.y;
    const int tid  = threadIdx.x;
    const int is32 = sniff_is32(TW, tid);

    __shared__ float smM[2][2][Cn];
    __shared__ float smN[2][2];
    __shared__ unsigned int slast;
    if (tid < 64) {
        const int z = tid >> 5, r = tid & 31;
        smM[z][r >> 4][r & 15] = g_mean[z][b][r >> 4][r & 15];
    } else if (tid < 68) {
        const int k = tid - 64;
        smN[k >> 1][k & 1] = g_nm[k >> 1][b][k & 1];
    }
    __syncthreads();

    const float* Sb  = S + ((size_t)b << 20);
    const float* Tb  = T + ((size_t)b << 20);
    const int*   twb = TW + (is32 ? ((size_t)b << 16) : ((size_t)b << 17));
    const float nS0 = smN[0][0], nS1 = smN[0][1];
    const float nT0 = smN[1][0], nT1 = smN[1][1];

    const int p = tile * PPB + tid * 4;
    int c0, c1, c2, c3;
    load_cls4(twb, p, is32, c0, c1, c2, c3);
    const float s0 = (c0 == 0) ? 1.f : -1.f;
    const float s1 = (c1 == 0) ? 1.f : -1.f;
    const float s2 = (c2 == 0) ? 1.f : -1.f;
    const float s3 = (c3 == 0) ? 1.f : -1.f;

    float pcS0, pcS1, pcS2, pcS3;
    {   // ---- S (streamed) ----
        float n0 = 0.f, n1 = 0.f, n2 = 0.f, n3 = 0.f;
        float dA0 = 0.f, dB0 = 0.f, dA1 = 0.f, dB1 = 0.f;
        float dA2 = 0.f, dB2 = 0.f, dA3 = 0.f, dB3 = 0.f;
#pragma unroll
        for (int c = 0; c < Cn; c++) {
            const float4 v = *(const float4*)(Sb + ((size_t)c << 16) + p);
            const float mA = smM[0][0][c], mB = smM[0][1][c];
            n0 = fmaf(v.x, v.x, n0); n1 = fmaf(v.y, v.y, n1);
            n2 = fmaf(v.z, v.z, n2); n3 = fmaf(v.w, v.w, n3);
            dA0 = fmaf(v.x, mA, dA0); dB0 = fmaf(v.x, mB, dB0);
            dA1 = fmaf(v.y, mA, dA1); dB1 = fmaf(v.y, mB, dB1);
            dA2 = fmaf(v.z, mA, dA2); dB2 = fmaf(v.z, mB, dB2);
            dA3 = fmaf(v.w, mA, dA3); dB3 = fmaf(v.w, mB, dB3);
        }
        const float i0 = rsqrtf(fmaxf(n0, 1e-24f)), i1 = rsqrtf(fmaxf(n1, 1e-24f));
        const float i2 = rsqrtf(fmaxf(n2, 1e-24f)), i3 = rsqrtf(fmaxf(n3, 1e-24f));
        const float f0 = sqrtf(n0) * i0, f1 = sqrtf(n1) * i1;
        const float f2 = sqrtf(n2) * i2, f3 = sqrtf(n3) * i3;
        const float cd0 = (dA0 * i0) / fmaxf(f0 * nS0, 1e-8f) - (dB0 * i0) / fmaxf(f0 * nS1, 1e-8f);
        const float cd1 = (dA1 * i1) / fmaxf(f1 * nS0, 1e-8f) - (dB1 * i1) / fmaxf(f1 * nS1, 1e-8f);
        const float cd2 = (dA2 * i2) / fmaxf(f2 * nS0, 1e-8f) - (dB2 * i2) / fmaxf(f2 * nS1, 1e-8f);
        const float cd3 = (dA3 * i3) / fmaxf(f3 * nS0, 1e-8f) - (dB3 * i3) / fmaxf(f3 * nS1, 1e-8f);
        pcS0 = expf(s0 * cd0); pcS1 = expf(s1 * cd1);
        pcS2 = expf(s2 * cd2); pcS3 = expf(s3 * cd3);
    }
    float acc;
    {   // ---- T (streamed) ----
        float n0 = 0.f, n1 = 0.f, n2 = 0.f, n3 = 0.f;
        float dA0 = 0.f, dB0 = 0.f, dA1 = 0.f, dB1 = 0.f;
        float dA2 = 0.f, dB2 = 0.f, dA3 = 0.f, dB3 = 0.f;
#pragma unroll
        for (int c = 0; c < Cn; c++) {
            const float4 v = *(const float4*)(Tb + ((size_t)c << 16) + p);
            const float mA = smM[1][0][c], mB = smM[1][1][c];
            n0 = fmaf(v.x, v.x, n0); n1 = fmaf(v.y, v.y, n1);
            n2 = fmaf(v.z, v.z, n2); n3 = fmaf(v.w, v.w, n3);
            dA0 = fmaf(v.x, mA, dA0); dB0 = fmaf(v.x, mB, dB0);
            dA1 = fmaf(v.y, mA, dA1); dB1 = fmaf(v.y, mB, dB1);
            dA2 = fmaf(v.z, mA, dA2); dB2 = fmaf(v.z, mB, dB2);
            dA3 = fmaf(v.w, mA, dA3); dB3 = fmaf(v.w, mB, dB3);
        }
        const float i0 = rsqrtf(fmaxf(n0, 1e-24f)), i1 = rsqrtf(fmaxf(n1, 1e-24f));
        const float i2 = rsqrtf(fmaxf(n2, 1e-24f)), i3 = rsqrtf(fmaxf(n3, 1e-24f));
        const float f0 = sqrtf(n0) * i0, f1 = sqrtf(n1) * i1;
        const float f2 = sqrtf(n2) * i2, f3 = sqrtf(n3) * i3;
        const float cd0 = (dA0 * i0) / fmaxf(f0 * nT0, 1e-8f) - (dB0 * i0) / fmaxf(f0 * nT1, 1e-8f);
        const float cd1 = (dA1 * i1) / fmaxf(f1 * nT0, 1e-8f) - (dB1 * i1) / fmaxf(f1 * nT1, 1e-8f);
        const float cd2 = (dA2 * i2) / fmaxf(f2 * nT0, 1e-8f) - (dB2 * i2) / fmaxf(f2 * nT1, 1e-8f);
        const float cd3 = (dA3 * i3) / fmaxf(f3 * nT0, 1e-8f) - (dB3 * i3) / fmaxf(f3 * nT1, 1e-8f);
        const float d0 = pcS0 - expf(s0 * cd0);
        const float d1 = pcS1 - expf(s1 * cd1);
        const float d2 = pcS2 - expf(s2 * cd2);
        const float d3 = pcS3 - expf(s3 * cd3);
        acc = fmaf(d0, d0, d1 * d1) + fmaf(d2, d2, d3 * d3);
    }

    // Block reduce MSE partial, then last-block final reduction.
    __shared__ float smse[THR / 32];
    acc = wred(acc);
    const int lane = tid & 31, w = tid >> 5;
    if (lane == 0) smse[w] = acc;
    __syncthreads();
    const int gid = b * T3 + tile;
    if (tid == 0) {
        float sv = 0.f;
#pragma unroll
        for (int ww = 0; ww < THR / 32; ww++) sv += smse[ww];
        g_msep[gid] = sv;
        __threadfence();
        const unsigned int old = atomicAdd(&g_done, 1u);
        slast = (old == (unsigned int)(Bn * T3 - 1)) ? 1u : 0u;
    }
    __syncthreads();

    if (slast) {
        volatile float* mp = &g_msep[0];
        double d = 0.0;
#pragma unroll
        for (int k = 0; k < (Bn * T3) / THR; k++)
            d += (double)mp[tid * ((Bn * T3) / THR) + k];
        d = wredd(d);
        __shared__ double sd[THR / 32];
        if (lane == 0) sd[w] = d;
        __syncthreads();
        if (tid == 0) {
            double tot = 0.0;
#pragma unroll
            for (int ww = 0; ww < THR / 32; ww++) tot += sd[ww];
            out[0] = (float)(tot * (1.0 / ((double)Bn * (double)HWn)));
            g_done = 0;   // reset for next graph replay
        }
    }
}

extern "C" void kernel_launch(void* const* d_in, const int* in_sizes, int n_in,
                              void* d_out, int out_size) {
    const float* S  = (const float*)d_in[0];
    const float* T  = (const float*)d_in[1];
    const int*   TW = (const int*)d_in[2];
    float* out = (float*)d_out;

    dim3 g1(T1, Bn, 2);
    pass1_kernel<<<g1, THR>>>(S, T, TW);
    dim3 gf(Bn, 2);
    finalize_kernel<<<gf, 256>>>();
    dim3 g3(T3, Bn);
    pass3_kernel<<<g3, THR>>>(S, T, TW, out);
}